// round 10
// baseline (speedup 1.0000x reference)
#include <cuda_runtime.h>
#include <cuda_fp16.h>
#include <math.h>

#define NN 100000
#define EE 1200000
#define CH 128
#define CAP 64            // bucket capacity per node (Poisson(12) -> P(deg>=64) ~ 1e-28)
#define APAD2 136         // padded half-stride for smem tiles (conflict-free frags)

// ---------------- device scratch ----------------
__device__ int g_degP[NN], g_degN[NN];
__device__ int g_colP[(size_t)NN * CAP], g_colN[(size_t)NN * CAP];
__device__ __half g_U[(size_t)NN * CH];
__device__ __half g_V[(size_t)NN * CH];
__device__ float g_R[(size_t)NN * CH];
__device__ float g_Z[(size_t)NN * CH];
__device__ int g_is64;

// ---------------- dtype detection ----------------
__global__ void detect_kernel(const unsigned int* __restrict__ p) {
    __shared__ int bad;
    if (threadIdx.x == 0) bad = 0;
    __syncthreads();
    if (p[threadIdx.x * 2 + 1] != 0u) bad = 1;
    __syncthreads();
    if (threadIdx.x == 0) g_is64 = (bad == 0) ? 1 : 0;
}

// ---------------- bucketed CSR fill (single pass, no scan) ----------------
__global__ void fillb_kernel(const void* __restrict__ e1, const void* __restrict__ e2,
                             int E) {
    int e = blockIdx.x * blockDim.x + threadIdx.x;
    if (e >= E) return;
    const void* ed = blockIdx.y ? e2 : e1;
    int* deg = blockIdx.y ? g_degN : g_degP;
    int* col = blockIdx.y ? g_colN : g_colP;
    int s, d;
    if (g_is64) {
        s = (int)((const long long*)ed)[e];
        d = (int)((const long long*)ed)[(size_t)E + e];
    } else {
        s = ((const int*)ed)[e];
        d = ((const int*)ed)[(size_t)E + e];
    }
    int slot = atomicAdd(&deg[d], 1);
    if (slot < CAP) col[(size_t)d * CAP + slot] = s;
}

// ---------------- fused-A tensor-core GEMM -------------------------------
// Stages A (n x K, fp32 -> fp16) once per block, then loops over up to 4
// weight matrices (K x 64) sharing that A. HMMA 16x8x16, fp32 accumulate.
struct GemmJob { const float* W; const float* bias; void* O; int half_out; };
struct GemmParamsF {
    const float* A0; const float* A1;
    GemmJob j[2][4];
    int njobs; int K; int nrows;
};

__device__ __forceinline__ void mma16816(float* c, const unsigned* a, const unsigned* b) {
    asm volatile(
        "mma.sync.aligned.m16n8k16.row.col.f32.f16.f16.f32 "
        "{%0,%1,%2,%3}, {%4,%5,%6,%7}, {%8,%9}, {%0,%1,%2,%3};"
        : "+f"(c[0]), "+f"(c[1]), "+f"(c[2]), "+f"(c[3])
        : "r"(a[0]), "r"(a[1]), "r"(a[2]), "r"(a[3]), "r"(b[0]), "r"(b[1]));
}

__global__ void __launch_bounds__(256) gemm_fused(GemmParamsF p) {
    extern __shared__ __half sm[];
    __half* As = sm;                     // [128][APAD2]
    __half* Bs = sm + 128 * APAD2;       // [64][APAD2]
    const float* A = blockIdx.y ? p.A1 : p.A0;
    const GemmJob* jobs = p.j[blockIdx.y];
    int K = p.K;
    int row0 = blockIdx.x * 128;
    int t = threadIdx.x;
    int lane = t & 31;
    int warp = t >> 5;
    int g = lane >> 2;
    int tg = lane & 3;
    int wr = warp >> 1;
    int wc = warp & 1;

    // stage A once: 128 rows x K halfs
    int kq = K >> 2;               // float4 groups per row
    int tot = 128 * kq;
    for (int idx = t; idx < tot; idx += 256) {
        int r = idx / kq;
        int cg = (idx - r * kq) * 4;
        float4 v = make_float4(0.f, 0.f, 0.f, 0.f);
        if (row0 + r < p.nrows)
            v = *(const float4*)(A + (size_t)(row0 + r) * CH + cg);
        __half2 h0 = __floats2half2_rn(v.x, v.y);
        __half2 h1 = __floats2half2_rn(v.z, v.w);
        uint2 pk; pk.x = *(unsigned*)&h0; pk.y = *(unsigned*)&h1;
        *(uint2*)&As[r * APAD2 + cg] = pk;
    }
    __syncthreads();

    for (int w = 0; w < p.njobs; w++) {
        GemmJob jb = jobs[w];
        // stage B transposed: W [K][64] -> Bs[n][k]
        int btot = K * 16;
        for (int idx = t; idx < btot; idx += 256) {
            int k = idx >> 4;
            int ng = (idx & 15) * 4;
            float4 v = *(const float4*)(jb.W + (size_t)k * 64 + ng);
            Bs[(ng + 0) * APAD2 + k] = __float2half_rn(v.x);
            Bs[(ng + 1) * APAD2 + k] = __float2half_rn(v.y);
            Bs[(ng + 2) * APAD2 + k] = __float2half_rn(v.z);
            Bs[(ng + 3) * APAD2 + k] = __float2half_rn(v.w);
        }
        __syncthreads();

        float acc[2][4][4];
        #pragma unroll
        for (int m = 0; m < 2; m++)
            #pragma unroll
            for (int nt = 0; nt < 4; nt++)
                #pragma unroll
                for (int i = 0; i < 4; i++) acc[m][nt][i] = 0.f;

        for (int kk = 0; kk < K; kk += 16) {
            unsigned a[2][4];
            #pragma unroll
            for (int m = 0; m < 2; m++) {
                int ar = wr * 32 + m * 16;
                a[m][0] = *(const unsigned*)&As[(ar + g) * APAD2 + kk + tg * 2];
                a[m][1] = *(const unsigned*)&As[(ar + g + 8) * APAD2 + kk + tg * 2];
                a[m][2] = *(const unsigned*)&As[(ar + g) * APAD2 + kk + tg * 2 + 8];
                a[m][3] = *(const unsigned*)&As[(ar + g + 8) * APAD2 + kk + tg * 2 + 8];
            }
            unsigned b[4][2];
            #pragma unroll
            for (int nt = 0; nt < 4; nt++) {
                int br = wc * 32 + nt * 8 + g;
                b[nt][0] = *(const unsigned*)&Bs[br * APAD2 + kk + tg * 2];
                b[nt][1] = *(const unsigned*)&Bs[br * APAD2 + kk + tg * 2 + 8];
            }
            #pragma unroll
            for (int m = 0; m < 2; m++)
                #pragma unroll
                for (int nt = 0; nt < 4; nt++)
                    mma16816(acc[m][nt], a[m], b[nt]);
        }

        // epilogue
        float bb0[4], bb1[4];
        #pragma unroll
        for (int nt = 0; nt < 4; nt++) {
            int col = wc * 32 + nt * 8 + tg * 2;
            bb0[nt] = jb.bias ? jb.bias[col] : 0.f;
            bb1[nt] = jb.bias ? jb.bias[col + 1] : 0.f;
        }
        #pragma unroll
        for (int m = 0; m < 2; m++) {
            int r1 = row0 + wr * 32 + m * 16 + g;
            int r2 = r1 + 8;
            #pragma unroll
            for (int nt = 0; nt < 4; nt++) {
                int col = wc * 32 + nt * 8 + tg * 2;
                if (jb.half_out) {
                    __half* O = (__half*)jb.O;
                    if (r1 < p.nrows) {
                        __half2 h = __floats2half2_rn(acc[m][nt][0] + bb0[nt], acc[m][nt][1] + bb1[nt]);
                        *(__half2*)(O + (size_t)r1 * CH + col) = h;
                    }
                    if (r2 < p.nrows) {
                        __half2 h = __floats2half2_rn(acc[m][nt][2] + bb0[nt], acc[m][nt][3] + bb1[nt]);
                        *(__half2*)(O + (size_t)r2 * CH + col) = h;
                    }
                } else {
                    float* O = (float*)jb.O;
                    if (r1 < p.nrows) {
                        float2 f = make_float2(acc[m][nt][0] + bb0[nt], acc[m][nt][1] + bb1[nt]);
                        *(float2*)(O + (size_t)r1 * CH + col) = f;
                    }
                    if (r2 < p.nrows) {
                        float2 f = make_float2(acc[m][nt][2] + bb0[nt], acc[m][nt][3] + bb1[nt]);
                        *(float2*)(O + (size_t)r2 * CH + col) = f;
                    }
                }
            }
        }
        __syncthreads();   // before restaging Bs
    }
}

// ---------------- layer-0 aggregation: 1 warp per node --------------------
__global__ void agg0_kernel(int n, float* __restrict__ Z) {
    int w = (blockIdx.x * blockDim.x + threadIdx.x) >> 5;
    if (w >= n) return;
    int lane = threadIdx.x & 31;
    int c = lane * 2;

    int dp = g_degP[w];
    int b = w * CAP, e = b + (dp < CAP ? dp : CAP);
    float invp = 1.0f / (float)(dp > 0 ? dp : 1);
    float sx0 = 0.f, sy0 = 0.f, sx1 = 0.f, sy1 = 0.f;
    int i = b;
    for (; i + 2 <= e; i += 2) {
        int ia = g_colP[i], ib = g_colP[i + 1];
        float2 ga = __half22float2(*(const __half2*)(g_U + (size_t)ia * CH + c));
        float2 gb = __half22float2(*(const __half2*)(g_U + (size_t)ib * CH + c));
        sx0 += ga.x; sy0 += ga.y; sx1 += gb.x; sy1 += gb.y;
    }
    if (i < e) {
        float2 ga = __half22float2(*(const __half2*)(g_U + (size_t)g_colP[i] * CH + c));
        sx0 += ga.x; sy0 += ga.y;
    }
    float sumpx = sx0 + sx1, sumpy = sy0 + sy1;

    int dn = g_degN[w];
    b = w * CAP; e = b + (dn < CAP ? dn : CAP);
    float invn = 1.0f / (float)(dn > 0 ? dn : 1);
    float tx0 = 0.f, ty0 = 0.f, tx1 = 0.f, ty1 = 0.f;
    i = b;
    for (; i + 2 <= e; i += 2) {
        int ia = g_colN[i], ib = g_colN[i + 1];
        float2 ga = __half22float2(*(const __half2*)(g_U + (size_t)ia * CH + 64 + c));
        float2 gb = __half22float2(*(const __half2*)(g_U + (size_t)ib * CH + 64 + c));
        tx0 += ga.x; ty0 += ga.y; tx1 += gb.x; ty1 += gb.y;
    }
    if (i < e) {
        float2 ga = __half22float2(*(const __half2*)(g_U + (size_t)g_colN[i] * CH + 64 + c));
        tx0 += ga.x; ty0 += ga.y;
    }
    float sumnx = tx0 + tx1, sumny = ty0 + ty1;

    float2 r0 = *(const float2*)(g_R + (size_t)w * CH + c);
    float2 r1 = *(const float2*)(g_R + (size_t)w * CH + 64 + c);
    float2 zp, zn;
    zp.x = tanhf(r0.x + invp * sumpx);
    zp.y = tanhf(r0.y + invp * sumpy);
    zn.x = tanhf(r1.x + invn * sumnx);
    zn.y = tanhf(r1.y + invn * sumny);
    *(float2*)(Z + (size_t)w * CH + c) = zp;
    *(float2*)(Z + (size_t)w * CH + 64 + c) = zn;
}

// ---------------- loop-layer aggregation: 1 warp per node -----------------
__global__ void aggl_kernel(int n, float* __restrict__ out) {
    int w = (blockIdx.x * blockDim.x + threadIdx.x) >> 5;
    if (w >= n) return;
    int lane = threadIdx.x & 31;
    int c = lane * 4;

    int dp = g_degP[w];
    int b = w * CAP, e = b + (dp < CAP ? dp : CAP);
    float invp = 1.0f / (float)(dp > 0 ? dp : 1);
    float4 s0 = make_float4(0.f, 0.f, 0.f, 0.f);
    float4 s1 = make_float4(0.f, 0.f, 0.f, 0.f);
    int i = b;
    for (; i + 2 <= e; i += 2) {
        int ia = g_colP[i], ib = g_colP[i + 1];
        uint2 pa = *(const uint2*)(g_U + (size_t)ia * CH + c);
        uint2 pb = *(const uint2*)(g_U + (size_t)ib * CH + c);
        float2 a0 = __half22float2(*(__half2*)&pa.x);
        float2 a1 = __half22float2(*(__half2*)&pa.y);
        float2 b0 = __half22float2(*(__half2*)&pb.x);
        float2 b1 = __half22float2(*(__half2*)&pb.y);
        s0.x += a0.x; s0.y += a0.y; s0.z += a1.x; s0.w += a1.y;
        s1.x += b0.x; s1.y += b0.y; s1.z += b1.x; s1.w += b1.y;
    }
    if (i < e) {
        uint2 pa = *(const uint2*)(g_U + (size_t)g_colP[i] * CH + c);
        float2 a0 = __half22float2(*(__half2*)&pa.x);
        float2 a1 = __half22float2(*(__half2*)&pa.y);
        s0.x += a0.x; s0.y += a0.y; s0.z += a1.x; s0.w += a1.y;
    }

    int dn = g_degN[w];
    b = w * CAP; e = b + (dn < CAP ? dn : CAP);
    float invn = 1.0f / (float)(dn > 0 ? dn : 1);
    float4 t0 = make_float4(0.f, 0.f, 0.f, 0.f);
    float4 t1 = make_float4(0.f, 0.f, 0.f, 0.f);
    i = b;
    for (; i + 2 <= e; i += 2) {
        int ia = g_colN[i], ib = g_colN[i + 1];
        uint2 pa = *(const uint2*)(g_V + (size_t)ia * CH + c);
        uint2 pb = *(const uint2*)(g_V + (size_t)ib * CH + c);
        float2 a0 = __half22float2(*(__half2*)&pa.x);
        float2 a1 = __half22float2(*(__half2*)&pa.y);
        float2 b0 = __half22float2(*(__half2*)&pb.x);
        float2 b1 = __half22float2(*(__half2*)&pb.y);
        t0.x += a0.x; t0.y += a0.y; t0.z += a1.x; t0.w += a1.y;
        t1.x += b0.x; t1.y += b0.y; t1.z += b1.x; t1.w += b1.y;
    }
    if (i < e) {
        uint2 pa = *(const uint2*)(g_V + (size_t)g_colN[i] * CH + c);
        float2 a0 = __half22float2(*(__half2*)&pa.x);
        float2 a1 = __half22float2(*(__half2*)&pa.y);
        t0.x += a0.x; t0.y += a0.y; t0.z += a1.x; t0.w += a1.y;
    }

    float4 r = *(const float4*)(g_R + (size_t)w * CH + c);
    float4 o;
    o.x = tanhf(r.x + invp * (s0.x + s1.x) + invn * (t0.x + t1.x));
    o.y = tanhf(r.y + invp * (s0.y + s1.y) + invn * (t0.y + t1.y));
    o.z = tanhf(r.z + invp * (s0.z + s1.z) + invn * (t0.z + t1.z));
    o.w = tanhf(r.w + invp * (s0.w + s1.w) + invn * (t0.w + t1.w));
    *(float4*)(out + (size_t)w * CH + c) = o;
}

// ---------------- host driver --------------------------------------------
extern "C" void kernel_launch(void* const* d_in, const int* in_sizes, int n_in,
                              void* d_out, int out_size) {
    const float* x      = (const float*)d_in[0];
    const void*  pe     = d_in[1];
    const void*  nedge  = d_in[2];
    const float* Wp_l   = (const float*)d_in[3];
    const float* Wp_r   = (const float*)d_in[4];
    const float* bp     = (const float*)d_in[5];
    const float* Wn_l   = (const float*)d_in[6];
    const float* Wn_r   = (const float*)d_in[7];
    const float* bn     = (const float*)d_in[8];
    const float* Wl_pos = (const float*)d_in[9];
    const float* Wr_pos = (const float*)d_in[10];
    const float* b_pos  = (const float*)d_in[11];
    const float* Wl_neg = (const float*)d_in[12];
    const float* Wr_neg = (const float*)d_in[13];
    const float* b_neg  = (const float*)d_in[14];

    int n = in_sizes[0] / CH;
    int E = in_sizes[1] / 2;
    if (n > NN) n = NN;
    if (E > EE) E = EE;

    void *pU, *pV, *pR, *pZ, *pDegP, *pDegN;
    cudaGetSymbolAddress(&pU, g_U);
    cudaGetSymbolAddress(&pV, g_V);
    cudaGetSymbolAddress(&pR, g_R);
    cudaGetSymbolAddress(&pZ, g_Z);
    cudaGetSymbolAddress(&pDegP, g_degP);
    cudaGetSymbolAddress(&pDegN, g_degN);

    const int smemBytes = (128 + 64) * APAD2 * 2;   // 52224
    cudaFuncSetAttribute(gemm_fused, cudaFuncAttributeMaxDynamicSharedMemorySize, smemBytes);

    cudaMemsetAsync(pDegP, 0, n * sizeof(int));
    cudaMemsetAsync(pDegN, 0, n * sizeof(int));

    detect_kernel<<<1, 1024>>>((const unsigned int*)pe);

    int eg = (E + 255) / 256;
    fillb_kernel<<<dim3(eg, 2), 256>>>(pe, nedge, E);

    int mg = (n + 127) / 128;
    int wg = (n * 32 + 255) / 256;

    // layer 0: single fused launch, A = x shared by 4 weights
    GemmParamsF p0;
    p0.A0 = x; p0.A1 = x;
    p0.njobs = 4; p0.K = CH; p0.nrows = n;
    p0.j[0][0] = GemmJob{ Wp_l, nullptr, (void*)((__half*)pU),        1 };
    p0.j[0][1] = GemmJob{ Wn_l, nullptr, (void*)(((__half*)pU) + 64), 1 };
    p0.j[0][2] = GemmJob{ Wp_r, bp,      (void*)((float*)pR),         0 };
    p0.j[0][3] = GemmJob{ Wn_r, bn,      (void*)(((float*)pR) + 64),  0 };
    p0.j[1][0] = p0.j[0][0]; p0.j[1][1] = p0.j[0][1];
    p0.j[1][2] = p0.j[0][2]; p0.j[1][3] = p0.j[0][3];
    gemm_fused<<<dim3(mg, 1), 256, smemBytes>>>(p0);
    agg0_kernel<<<wg, 256>>>(n, (float*)pZ);

    // loop layers: one fused launch per layer; grid.y selects zp/zn
    for (int l = 0; l < 2; l++) {
        const float* zp = (const float*)pZ;
        const float* zn = (const float*)pZ + 64;
        GemmParamsF pl;
        pl.A0 = zp; pl.A1 = zn;
        pl.njobs = 3; pl.K = 64; pl.nrows = n;
        // A = zp jobs
        pl.j[0][0] = GemmJob{ Wl_pos + l * 8192,        nullptr,        (void*)((__half*)pU),        1 };
        pl.j[0][1] = GemmJob{ Wl_neg + l * 8192 + 4096, nullptr,        (void*)(((__half*)pV) + 64), 1 };
        pl.j[0][2] = GemmJob{ Wr_pos + l * 4096,        b_pos + l * 64, (void*)((float*)pR),         0 };
        pl.j[0][3] = pl.j[0][0];
        // A = zn jobs
        pl.j[1][0] = GemmJob{ Wl_neg + l * 8192,        nullptr,        (void*)(((__half*)pU) + 64), 1 };
        pl.j[1][1] = GemmJob{ Wl_pos + l * 8192 + 4096, nullptr,        (void*)((__half*)pV),        1 };
        pl.j[1][2] = GemmJob{ Wr_neg + l * 4096,        b_neg + l * 64, (void*)(((float*)pR) + 64),  0 };
        pl.j[1][3] = pl.j[1][0];
        gemm_fused<<<dim3(mg, 2), 256, smemBytes>>>(pl);

        float* outp = (l == 1) ? (float*)d_out : (float*)pZ;
        aggl_kernel<<<wg, 256>>>(n, outp);
    }
}

// round 14
// speedup vs baseline: 1.0601x; 1.0601x over previous
#include <cuda_runtime.h>
#include <cuda_fp16.h>
#include <math.h>

#define NN 100000
#define EE 1200000
#define CH 128
#define SCHUNK 512
#define MAXCHUNK 200

// ---------------- device scratch ----------------
__device__ int g_degP[NN], g_degN[NN], g_curP[NN], g_curN[NN];
__device__ int g_rpP[NN + 1], g_rpN[NN + 1];
__device__ int g_colP[EE], g_colN[EE];
__device__ int g_partP[MAXCHUNK], g_partN[MAXCHUNK];
__device__ __half g_U[(size_t)NN * CH];
__device__ __half g_V[(size_t)NN * CH];
__device__ float g_R[(size_t)NN * CH];
__device__ float g_Z[(size_t)NN * CH];
__device__ int g_is64;

// ---------------- dtype detection ----------------
__global__ void detect_kernel(const unsigned int* __restrict__ p) {
    __shared__ int bad;
    if (threadIdx.x == 0) bad = 0;
    __syncthreads();
    if (p[threadIdx.x * 2 + 1] != 0u) bad = 1;
    __syncthreads();
    if (threadIdx.x == 0) g_is64 = (bad == 0) ? 1 : 0;
}

// ---------------- CSR build (scan-based, dense) ----------------
__global__ void hist2_kernel(const void* __restrict__ e1, const void* __restrict__ e2,
                             int E) {
    int e = blockIdx.x * blockDim.x + threadIdx.x;
    if (e >= E) return;
    const void* ed = blockIdx.y ? e2 : e1;
    int* deg = blockIdx.y ? g_degN : g_degP;
    int d;
    if (g_is64) d = (int)((const long long*)ed)[(size_t)E + e];
    else        d = ((const int*)ed)[(size_t)E + e];
    atomicAdd(&deg[d], 1);
}

__global__ void __launch_bounds__(SCHUNK) scan_part_kernel(int n) {
    const int* deg = blockIdx.y ? g_degN : g_degP;
    int* part = blockIdx.y ? g_partN : g_partP;
    int t = threadIdx.x;
    int i = blockIdx.x * SCHUNK + t;
    int v = (i < n) ? deg[i] : 0;
    #pragma unroll
    for (int off = 16; off > 0; off >>= 1)
        v += __shfl_down_sync(0xffffffffu, v, off);
    __shared__ int ws[16];
    if ((t & 31) == 0) ws[t >> 5] = v;
    __syncthreads();
    if (t < 16) {
        int r = ws[t];
        #pragma unroll
        for (int off = 8; off > 0; off >>= 1)
            r += __shfl_down_sync(0x0000ffffu, r, off);
        if (t == 0) part[blockIdx.x] = r;
    }
}

__global__ void __launch_bounds__(256) scan_mid_kernel(int nchunk) {
    __shared__ int wt[8];
    int t = threadIdx.x;
    for (int a = 0; a < 2; a++) {
        int* part = a ? g_partN : g_partP;
        int v = (t < nchunk) ? part[t] : 0;
        int x = v;
        #pragma unroll
        for (int off = 1; off < 32; off <<= 1) {
            int y = __shfl_up_sync(0xffffffffu, x, off);
            if ((t & 31) >= off) x += y;
        }
        if ((t & 31) == 31) wt[t >> 5] = x;
        __syncthreads();
        if (t < 8) {
            int w = wt[t];
            #pragma unroll
            for (int off = 1; off < 8; off <<= 1) {
                int y = __shfl_up_sync(0x000000ffu, w, off);
                if (t >= off) w += y;
            }
            wt[t] = w;
        }
        __syncthreads();
        int incl = x + ((t >> 5) ? wt[(t >> 5) - 1] : 0);
        if (t < nchunk) part[t] = incl - v;
        __syncthreads();
    }
}

__global__ void __launch_bounds__(SCHUNK) scan_final_kernel(int n, int E) {
    const int* deg = blockIdx.y ? g_degN : g_degP;
    const int* part = blockIdx.y ? g_partN : g_partP;
    int* rp = blockIdx.y ? g_rpN : g_rpP;
    int* cur = blockIdx.y ? g_curN : g_curP;
    int t = threadIdx.x;
    int i = blockIdx.x * SCHUNK + t;
    int v = (i < n) ? deg[i] : 0;
    int x = v;
    #pragma unroll
    for (int off = 1; off < 32; off <<= 1) {
        int y = __shfl_up_sync(0xffffffffu, x, off);
        if ((t & 31) >= off) x += y;
    }
    __shared__ int ws[16];
    if ((t & 31) == 31) ws[t >> 5] = x;
    __syncthreads();
    if (t < 16) {
        int w = ws[t];
        #pragma unroll
        for (int off = 1; off < 16; off <<= 1) {
            int y = __shfl_up_sync(0x0000ffffu, w, off);
            if (t >= off) w += y;
        }
        ws[t] = w;
    }
    __syncthreads();
    int incl = x + ((t >> 5) ? ws[(t >> 5) - 1] : 0);
    int excl = incl - v + part[blockIdx.x];
    if (i < n) { rp[i] = excl; cur[i] = excl; }
    if (blockIdx.x == 0 && t == 0) rp[n] = E;
}

__global__ void fill2_kernel(const void* __restrict__ e1, const void* __restrict__ e2,
                             int E) {
    int e = blockIdx.x * blockDim.x + threadIdx.x;
    if (e >= E) return;
    const void* ed = blockIdx.y ? e2 : e1;
    int* cur = blockIdx.y ? g_curN : g_curP;
    int* col = blockIdx.y ? g_colN : g_colP;
    int s, d;
    if (g_is64) {
        s = (int)((const long long*)ed)[e];
        d = (int)((const long long*)ed)[(size_t)E + e];
    } else {
        s = ((const int*)ed)[e];
        d = ((const int*)ed)[(size_t)E + e];
    }
    int slot = atomicAdd(&cur[d], 1);
    col[slot] = s;
}

// ---------------- fused-A tensor-core GEMM -------------------------------
// Stages A (n x K, fp32 -> fp16) once per block (smem stride K+8), then
// loops over up to 4 weight matrices (K x 64). HMMA 16x8x16, fp32 accum.
struct GemmJob { const float* W; const float* bias; void* O; int half_out; };
struct GemmParamsF {
    const float* A0; const float* A1;
    GemmJob j[2][4];
    int njobs; int K; int nrows;
};

__device__ __forceinline__ void mma16816(float* c, const unsigned* a, const unsigned* b) {
    asm volatile(
        "mma.sync.aligned.m16n8k16.row.col.f32.f16.f16.f32 "
        "{%0,%1,%2,%3}, {%4,%5,%6,%7}, {%8,%9}, {%0,%1,%2,%3};"
        : "+f"(c[0]), "+f"(c[1]), "+f"(c[2]), "+f"(c[3])
        : "r"(a[0]), "r"(a[1]), "r"(a[2]), "r"(a[3]), "r"(b[0]), "r"(b[1]));
}

__global__ void __launch_bounds__(256) gemm_fused(GemmParamsF p) {
    extern __shared__ __half sm[];
    const int K = p.K;
    const int stride = K + 8;            // 136 for K=128, 72 for K=64 (both conflict-free)
    __half* As = sm;                     // [128][stride]
    __half* Bs = sm + 128 * stride;      // [64][stride]
    const float* A = blockIdx.y ? p.A1 : p.A0;
    const GemmJob* jobs = p.j[blockIdx.y];
    int row0 = blockIdx.x * 128;
    int t = threadIdx.x;
    int lane = t & 31;
    int warp = t >> 5;
    int g = lane >> 2;
    int tg = lane & 3;
    int wr = warp >> 1;
    int wc = warp & 1;

    // stage A once: 128 rows x K halfs
    int kq = K >> 2;               // float4 groups per row
    int tot = 128 * kq;
    for (int idx = t; idx < tot; idx += 256) {
        int r = idx / kq;
        int cg = (idx - r * kq) * 4;
        float4 v = make_float4(0.f, 0.f, 0.f, 0.f);
        if (row0 + r < p.nrows)
            v = *(const float4*)(A + (size_t)(row0 + r) * CH + cg);
        __half2 h0 = __floats2half2_rn(v.x, v.y);
        __half2 h1 = __floats2half2_rn(v.z, v.w);
        uint2 pk; pk.x = *(unsigned*)&h0; pk.y = *(unsigned*)&h1;
        *(uint2*)&As[r * stride + cg] = pk;
    }
    __syncthreads();

    for (int w = 0; w < p.njobs; w++) {
        GemmJob jb = jobs[w];
        // stage B transposed: W [K][64] -> Bs[n][k]
        int btot = K * 16;
        for (int idx = t; idx < btot; idx += 256) {
            int k = idx >> 4;
            int ng = (idx & 15) * 4;
            float4 v = *(const float4*)(jb.W + (size_t)k * 64 + ng);
            Bs[(ng + 0) * stride + k] = __float2half_rn(v.x);
            Bs[(ng + 1) * stride + k] = __float2half_rn(v.y);
            Bs[(ng + 2) * stride + k] = __float2half_rn(v.z);
            Bs[(ng + 3) * stride + k] = __float2half_rn(v.w);
        }
        __syncthreads();

        float acc[2][4][4];
        #pragma unroll
        for (int m = 0; m < 2; m++)
            #pragma unroll
            for (int nt = 0; nt < 4; nt++)
                #pragma unroll
                for (int i = 0; i < 4; i++) acc[m][nt][i] = 0.f;

        for (int kk = 0; kk < K; kk += 16) {
            unsigned a[2][4];
            #pragma unroll
            for (int m = 0; m < 2; m++) {
                int ar = wr * 32 + m * 16;
                a[m][0] = *(const unsigned*)&As[(ar + g) * stride + kk + tg * 2];
                a[m][1] = *(const unsigned*)&As[(ar + g + 8) * stride + kk + tg * 2];
                a[m][2] = *(const unsigned*)&As[(ar + g) * stride + kk + tg * 2 + 8];
                a[m][3] = *(const unsigned*)&As[(ar + g + 8) * stride + kk + tg * 2 + 8];
            }
            unsigned b[4][2];
            #pragma unroll
            for (int nt = 0; nt < 4; nt++) {
                int br = wc * 32 + nt * 8 + g;
                b[nt][0] = *(const unsigned*)&Bs[br * stride + kk + tg * 2];
                b[nt][1] = *(const unsigned*)&Bs[br * stride + kk + tg * 2 + 8];
            }
            #pragma unroll
            for (int m = 0; m < 2; m++)
                #pragma unroll
                for (int nt = 0; nt < 4; nt++)
                    mma16816(acc[m][nt], a[m], b[nt]);
        }

        // epilogue
        float bb0[4], bb1[4];
        #pragma unroll
        for (int nt = 0; nt < 4; nt++) {
            int col = wc * 32 + nt * 8 + tg * 2;
            bb0[nt] = jb.bias ? jb.bias[col] : 0.f;
            bb1[nt] = jb.bias ? jb.bias[col + 1] : 0.f;
        }
        #pragma unroll
        for (int m = 0; m < 2; m++) {
            int r1 = row0 + wr * 32 + m * 16 + g;
            int r2 = r1 + 8;
            #pragma unroll
            for (int nt = 0; nt < 4; nt++) {
                int col = wc * 32 + nt * 8 + tg * 2;
                if (jb.half_out) {
                    __half* O = (__half*)jb.O;
                    if (r1 < p.nrows) {
                        __half2 h = __floats2half2_rn(acc[m][nt][0] + bb0[nt], acc[m][nt][1] + bb1[nt]);
                        *(__half2*)(O + (size_t)r1 * CH + col) = h;
                    }
                    if (r2 < p.nrows) {
                        __half2 h = __floats2half2_rn(acc[m][nt][2] + bb0[nt], acc[m][nt][3] + bb1[nt]);
                        *(__half2*)(O + (size_t)r2 * CH + col) = h;
                    }
                } else {
                    float* O = (float*)jb.O;
                    if (r1 < p.nrows) {
                        float2 f = make_float2(acc[m][nt][0] + bb0[nt], acc[m][nt][1] + bb1[nt]);
                        *(float2*)(O + (size_t)r1 * CH + col) = f;
                    }
                    if (r2 < p.nrows) {
                        float2 f = make_float2(acc[m][nt][2] + bb0[nt], acc[m][nt][3] + bb1[nt]);
                        *(float2*)(O + (size_t)r2 * CH + col) = f;
                    }
                }
            }
        }
        __syncthreads();   // before restaging Bs
    }
}

// ---------------- layer-0 aggregation: 1 warp per node --------------------
__global__ void agg0_kernel(int n, float* __restrict__ Z) {
    int w = (blockIdx.x * blockDim.x + threadIdx.x) >> 5;
    if (w >= n) return;
    int lane = threadIdx.x & 31;
    int c = lane * 2;

    float sx0 = 0.f, sy0 = 0.f, sx1 = 0.f, sy1 = 0.f;
    int b = g_rpP[w], e = g_rpP[w + 1];
    float invp = 1.0f / (float)((e - b) > 0 ? (e - b) : 1);
    int i = b;
    for (; i + 2 <= e; i += 2) {
        int ia = g_colP[i], ib = g_colP[i + 1];
        float2 ga = __half22float2(*(const __half2*)(g_U + (size_t)ia * CH + c));
        float2 gb = __half22float2(*(const __half2*)(g_U + (size_t)ib * CH + c));
        sx0 += ga.x; sy0 += ga.y; sx1 += gb.x; sy1 += gb.y;
    }
    if (i < e) {
        float2 ga = __half22float2(*(const __half2*)(g_U + (size_t)g_colP[i] * CH + c));
        sx0 += ga.x; sy0 += ga.y;
    }
    float sumpx = sx0 + sx1, sumpy = sy0 + sy1;

    float tx0 = 0.f, ty0 = 0.f, tx1 = 0.f, ty1 = 0.f;
    b = g_rpN[w]; e = g_rpN[w + 1];
    float invn = 1.0f / (float)((e - b) > 0 ? (e - b) : 1);
    i = b;
    for (; i + 2 <= e; i += 2) {
        int ia = g_colN[i], ib = g_colN[i + 1];
        float2 ga = __half22float2(*(const __half2*)(g_U + (size_t)ia * CH + 64 + c));
        float2 gb = __half22float2(*(const __half2*)(g_U + (size_t)ib * CH + 64 + c));
        tx0 += ga.x; ty0 += ga.y; tx1 += gb.x; ty1 += gb.y;
    }
    if (i < e) {
        float2 ga = __half22float2(*(const __half2*)(g_U + (size_t)g_colN[i] * CH + 64 + c));
        tx0 += ga.x; ty0 += ga.y;
    }
    float sumnx = tx0 + tx1, sumny = ty0 + ty1;

    float2 r0 = *(const float2*)(g_R + (size_t)w * CH + c);
    float2 r1 = *(const float2*)(g_R + (size_t)w * CH + 64 + c);
    float2 zp, zn;
    zp.x = tanhf(r0.x + invp * sumpx);
    zp.y = tanhf(r0.y + invp * sumpy);
    zn.x = tanhf(r1.x + invn * sumnx);
    zn.y = tanhf(r1.y + invn * sumny);
    *(float2*)(Z + (size_t)w * CH + c) = zp;
    *(float2*)(Z + (size_t)w * CH + 64 + c) = zn;
}

// ---------------- loop-layer aggregation: 1 warp per node -----------------
__global__ void aggl_kernel(int n, float* __restrict__ out) {
    int w = (blockIdx.x * blockDim.x + threadIdx.x) >> 5;
    if (w >= n) return;
    int lane = threadIdx.x & 31;
    int c = lane * 4;

    float4 s0 = make_float4(0.f, 0.f, 0.f, 0.f);
    float4 s1 = make_float4(0.f, 0.f, 0.f, 0.f);
    int b = g_rpP[w], e = g_rpP[w + 1];
    float invp = 1.0f / (float)((e - b) > 0 ? (e - b) : 1);
    int i = b;
    for (; i + 2 <= e; i += 2) {
        int ia = g_colP[i], ib = g_colP[i + 1];
        uint2 pa = *(const uint2*)(g_U + (size_t)ia * CH + c);
        uint2 pb = *(const uint2*)(g_U + (size_t)ib * CH + c);
        float2 a0 = __half22float2(*(__half2*)&pa.x);
        float2 a1 = __half22float2(*(__half2*)&pa.y);
        float2 b0 = __half22float2(*(__half2*)&pb.x);
        float2 b1 = __half22float2(*(__half2*)&pb.y);
        s0.x += a0.x; s0.y += a0.y; s0.z += a1.x; s0.w += a1.y;
        s1.x += b0.x; s1.y += b0.y; s1.z += b1.x; s1.w += b1.y;
    }
    if (i < e) {
        uint2 pa = *(const uint2*)(g_U + (size_t)g_colP[i] * CH + c);
        float2 a0 = __half22float2(*(__half2*)&pa.x);
        float2 a1 = __half22float2(*(__half2*)&pa.y);
        s0.x += a0.x; s0.y += a0.y; s0.z += a1.x; s0.w += a1.y;
    }

    float4 t0 = make_float4(0.f, 0.f, 0.f, 0.f);
    float4 t1 = make_float4(0.f, 0.f, 0.f, 0.f);
    b = g_rpN[w]; e = g_rpN[w + 1];
    float invn = 1.0f / (float)((e - b) > 0 ? (e - b) : 1);
    i = b;
    for (; i + 2 <= e; i += 2) {
        int ia = g_colN[i], ib = g_colN[i + 1];
        uint2 pa = *(const uint2*)(g_V + (size_t)ia * CH + c);
        uint2 pb = *(const uint2*)(g_V + (size_t)ib * CH + c);
        float2 a0 = __half22float2(*(__half2*)&pa.x);
        float2 a1 = __half22float2(*(__half2*)&pa.y);
        float2 b0 = __half22float2(*(__half2*)&pb.x);
        float2 b1 = __half22float2(*(__half2*)&pb.y);
        t0.x += a0.x; t0.y += a0.y; t0.z += a1.x; t0.w += a1.y;
        t1.x += b0.x; t1.y += b0.y; t1.z += b1.x; t1.w += b1.y;
    }
    if (i < e) {
        uint2 pa = *(const uint2*)(g_V + (size_t)g_colN[i] * CH + c);
        float2 a0 = __half22float2(*(__half2*)&pa.x);
        float2 a1 = __half22float2(*(__half2*)&pa.y);
        t0.x += a0.x; t0.y += a0.y; t0.z += a1.x; t0.w += a1.y;
    }

    float4 r = *(const float4*)(g_R + (size_t)w * CH + c);
    float4 o;
    o.x = tanhf(r.x + invp * (s0.x + s1.x) + invn * (t0.x + t1.x));
    o.y = tanhf(r.y + invp * (s0.y + s1.y) + invn * (t0.y + t1.y));
    o.z = tanhf(r.z + invp * (s0.z + s1.z) + invn * (t0.z + t1.z));
    o.w = tanhf(r.w + invp * (s0.w + s1.w) + invn * (t0.w + t1.w));
    *(float4*)(out + (size_t)w * CH + c) = o;
}

// ---------------- host driver --------------------------------------------
extern "C" void kernel_launch(void* const* d_in, const int* in_sizes, int n_in,
                              void* d_out, int out_size) {
    const float* x      = (const float*)d_in[0];
    const void*  pe     = d_in[1];
    const void*  nedge  = d_in[2];
    const float* Wp_l   = (const float*)d_in[3];
    const float* Wp_r   = (const float*)d_in[4];
    const float* bp     = (const float*)d_in[5];
    const float* Wn_l   = (const float*)d_in[6];
    const float* Wn_r   = (const float*)d_in[7];
    const float* bn     = (const float*)d_in[8];
    const float* Wl_pos = (const float*)d_in[9];
    const float* Wr_pos = (const float*)d_in[10];
    const float* b_pos  = (const float*)d_in[11];
    const float* Wl_neg = (const float*)d_in[12];
    const float* Wr_neg = (const float*)d_in[13];
    const float* b_neg  = (const float*)d_in[14];

    int n = in_sizes[0] / CH;
    int E = in_sizes[1] / 2;
    if (n > NN) n = NN;
    if (E > EE) E = EE;

    void *pU, *pV, *pR, *pZ, *pDegP, *pDegN;
    cudaGetSymbolAddress(&pU, g_U);
    cudaGetSymbolAddress(&pV, g_V);
    cudaGetSymbolAddress(&pR, g_R);
    cudaGetSymbolAddress(&pZ, g_Z);
    cudaGetSymbolAddress(&pDegP, g_degP);
    cudaGetSymbolAddress(&pDegN, g_degN);

    const int smem0 = (128 + 64) * (CH + 8) * 2;   // K=128 -> 52224 B
    const int smemL = (128 + 64) * (64 + 8) * 2;   // K=64  -> 27648 B
    cudaFuncSetAttribute(gemm_fused, cudaFuncAttributeMaxDynamicSharedMemorySize, smem0);

    cudaMemsetAsync(pDegP, 0, n * sizeof(int));
    cudaMemsetAsync(pDegN, 0, n * sizeof(int));

    detect_kernel<<<1, 1024>>>((const unsigned int*)pe);

    int eg = (E + 255) / 256;
    int nchunk = (n + SCHUNK - 1) / SCHUNK;
    hist2_kernel<<<dim3(eg, 2), 256>>>(pe, nedge, E);
    scan_part_kernel<<<dim3(nchunk, 2), SCHUNK>>>(n);
    scan_mid_kernel<<<1, 256>>>(nchunk);
    scan_final_kernel<<<dim3(nchunk, 2), SCHUNK>>>(n, E);
    fill2_kernel<<<dim3(eg, 2), 256>>>(pe, nedge, E);

    int mg = (n + 127) / 128;
    int wg = (n * 32 + 255) / 256;

    // layer 0: single fused launch, A = x shared by 4 weights
    GemmParamsF p0;
    p0.A0 = x; p0.A1 = x;
    p0.njobs = 4; p0.K = CH; p0.nrows = n;
    p0.j[0][0] = GemmJob{ Wp_l, nullptr, (void*)((__half*)pU),        1 };
    p0.j[0][1] = GemmJob{ Wn_l, nullptr, (void*)(((__half*)pU) + 64), 1 };
    p0.j[0][2] = GemmJob{ Wp_r, bp,      (void*)((float*)pR),         0 };
    p0.j[0][3] = GemmJob{ Wn_r, bn,      (void*)(((float*)pR) + 64),  0 };
    p0.j[1][0] = p0.j[0][0]; p0.j[1][1] = p0.j[0][1];
    p0.j[1][2] = p0.j[0][2]; p0.j[1][3] = p0.j[0][3];
    gemm_fused<<<dim3(mg, 1), 256, smem0>>>(p0);
    agg0_kernel<<<wg, 256>>>(n, (float*)pZ);

    // loop layers: one fused launch per layer; grid.y selects zp/zn
    for (int l = 0; l < 2; l++) {
        const float* zp = (const float*)pZ;
        const float* zn = (const float*)pZ + 64;
        GemmParamsF pl;
        pl.A0 = zp; pl.A1 = zn;
        pl.njobs = 3; pl.K = 64; pl.nrows = n;
        // A = zp jobs
        pl.j[0][0] = GemmJob{ Wl_pos + l * 8192,        nullptr,        (void*)((__half*)pU),        1 };
        pl.j[0][1] = GemmJob{ Wl_neg + l * 8192 + 4096, nullptr,        (void*)(((__half*)pV) + 64), 1 };
        pl.j[0][2] = GemmJob{ Wr_pos + l * 4096,        b_pos + l * 64, (void*)((float*)pR),         0 };
        pl.j[0][3] = pl.j[0][0];
        // A = zn jobs
        pl.j[1][0] = GemmJob{ Wl_neg + l * 8192,        nullptr,        (void*)(((__half*)pU) + 64), 1 };
        pl.j[1][1] = GemmJob{ Wl_pos + l * 8192 + 4096, nullptr,        (void*)((__half*)pV),        1 };
        pl.j[1][2] = GemmJob{ Wr_neg + l * 4096,        b_neg + l * 64, (void*)(((float*)pR) + 64),  0 };
        pl.j[1][3] = pl.j[1][0];
        gemm_fused<<<dim3(mg, 2), 256, smemL>>>(pl);

        float* outp = (l == 1) ? (float*)d_out : (float*)pZ;
        aggl_kernel<<<wg, 256>>>(n, outp);
    }
}

// round 17
// speedup vs baseline: 1.1125x; 1.0495x over previous
#include <cuda_runtime.h>
#include <cuda_fp16.h>
#include <math.h>

#define NN 100000
#define EE 1200000
#define CH 128
#define SCHUNK 512
#define MAXCHUNK 200

// ---------------- device scratch ----------------
__device__ int g_degP[NN], g_degN[NN], g_curP[NN], g_curN[NN];
__device__ int g_rpP[NN + 1], g_rpN[NN + 1];
__device__ int g_colP[EE], g_colN[EE];
__device__ int g_partP[MAXCHUNK], g_partN[MAXCHUNK];
__device__ __half g_U[(size_t)NN * CH];
__device__ __half g_V[(size_t)NN * CH];
__device__ __half g_R[(size_t)NN * CH];
__device__ __half g_Z[(size_t)NN * CH];
__device__ int g_is64;

// ---------------- dtype detection ----------------
__global__ void detect_kernel(const unsigned int* __restrict__ p) {
    __shared__ int bad;
    if (threadIdx.x == 0) bad = 0;
    __syncthreads();
    if (p[threadIdx.x * 2 + 1] != 0u) bad = 1;
    __syncthreads();
    if (threadIdx.x == 0) g_is64 = (bad == 0) ? 1 : 0;
}

// ---------------- CSR build (scan-based, dense) ----------------
__global__ void hist2_kernel(const void* __restrict__ e1, const void* __restrict__ e2,
                             int E) {
    int e = blockIdx.x * blockDim.x + threadIdx.x;
    if (e >= E) return;
    const void* ed = blockIdx.y ? e2 : e1;
    int* deg = blockIdx.y ? g_degN : g_degP;
    int d;
    if (g_is64) d = (int)((const long long*)ed)[(size_t)E + e];
    else        d = ((const int*)ed)[(size_t)E + e];
    atomicAdd(&deg[d], 1);
}

__global__ void __launch_bounds__(SCHUNK) scan_part_kernel(int n) {
    const int* deg = blockIdx.y ? g_degN : g_degP;
    int* part = blockIdx.y ? g_partN : g_partP;
    int t = threadIdx.x;
    int i = blockIdx.x * SCHUNK + t;
    int v = (i < n) ? deg[i] : 0;
    #pragma unroll
    for (int off = 16; off > 0; off >>= 1)
        v += __shfl_down_sync(0xffffffffu, v, off);
    __shared__ int ws[16];
    if ((t & 31) == 0) ws[t >> 5] = v;
    __syncthreads();
    if (t < 16) {
        int r = ws[t];
        #pragma unroll
        for (int off = 8; off > 0; off >>= 1)
            r += __shfl_down_sync(0x0000ffffu, r, off);
        if (t == 0) part[blockIdx.x] = r;
    }
}

__global__ void __launch_bounds__(256) scan_mid_kernel(int nchunk) {
    __shared__ int wt[8];
    int t = threadIdx.x;
    for (int a = 0; a < 2; a++) {
        int* part = a ? g_partN : g_partP;
        int v = (t < nchunk) ? part[t] : 0;
        int x = v;
        #pragma unroll
        for (int off = 1; off < 32; off <<= 1) {
            int y = __shfl_up_sync(0xffffffffu, x, off);
            if ((t & 31) >= off) x += y;
        }
        if ((t & 31) == 31) wt[t >> 5] = x;
        __syncthreads();
        if (t < 8) {
            int w = wt[t];
            #pragma unroll
            for (int off = 1; off < 8; off <<= 1) {
                int y = __shfl_up_sync(0x000000ffu, w, off);
                if (t >= off) w += y;
            }
            wt[t] = w;
        }
        __syncthreads();
        int incl = x + ((t >> 5) ? wt[(t >> 5) - 1] : 0);
        if (t < nchunk) part[t] = incl - v;
        __syncthreads();
    }
}

__global__ void __launch_bounds__(SCHUNK) scan_final_kernel(int n, int E) {
    const int* deg = blockIdx.y ? g_degN : g_degP;
    const int* part = blockIdx.y ? g_partN : g_partP;
    int* rp = blockIdx.y ? g_rpN : g_rpP;
    int* cur = blockIdx.y ? g_curN : g_curP;
    int t = threadIdx.x;
    int i = blockIdx.x * SCHUNK + t;
    int v = (i < n) ? deg[i] : 0;
    int x = v;
    #pragma unroll
    for (int off = 1; off < 32; off <<= 1) {
        int y = __shfl_up_sync(0xffffffffu, x, off);
        if ((t & 31) >= off) x += y;
    }
    __shared__ int ws[16];
    if ((t & 31) == 31) ws[t >> 5] = x;
    __syncthreads();
    if (t < 16) {
        int w = ws[t];
        #pragma unroll
        for (int off = 1; off < 16; off <<= 1) {
            int y = __shfl_up_sync(0x0000ffffu, w, off);
            if (t >= off) w += y;
        }
        ws[t] = w;
    }
    __syncthreads();
    int incl = x + ((t >> 5) ? ws[(t >> 5) - 1] : 0);
    int excl = incl - v + part[blockIdx.x];
    if (i < n) { rp[i] = excl; cur[i] = excl; }
    if (blockIdx.x == 0 && t == 0) rp[n] = E;
}

__global__ void fill2_kernel(const void* __restrict__ e1, const void* __restrict__ e2,
                             int E) {
    int e = blockIdx.x * blockDim.x + threadIdx.x;
    if (e >= E) return;
    const void* ed = blockIdx.y ? e2 : e1;
    int* cur = blockIdx.y ? g_curN : g_curP;
    int* col = blockIdx.y ? g_colN : g_colP;
    int s, d;
    if (g_is64) {
        s = (int)((const long long*)ed)[e];
        d = (int)((const long long*)ed)[(size_t)E + e];
    } else {
        s = ((const int*)ed)[e];
        d = ((const int*)ed)[(size_t)E + e];
    }
    int slot = atomicAdd(&cur[d], 1);
    col[slot] = s;
}

// ---------------- fused-A tensor-core GEMM -------------------------------
// Stages A (n x K) once per block (fp32->fp16 convert, or direct fp16 copy
// when A is already half), then loops over up to 4 weight matrices (K x 64).
// HMMA 16x8x16, fp32 accumulate, fp16 output.
struct GemmJob { const float* W; const float* bias; __half* O; };
struct GemmParamsF {
    const void* A0; const void* A1;
    GemmJob j[2][4];
    int njobs; int K; int nrows; int a_half;
};

__device__ __forceinline__ void mma16816(float* c, const unsigned* a, const unsigned* b) {
    asm volatile(
        "mma.sync.aligned.m16n8k16.row.col.f32.f16.f16.f32 "
        "{%0,%1,%2,%3}, {%4,%5,%6,%7}, {%8,%9}, {%0,%1,%2,%3};"
        : "+f"(c[0]), "+f"(c[1]), "+f"(c[2]), "+f"(c[3])
        : "r"(a[0]), "r"(a[1]), "r"(a[2]), "r"(a[3]), "r"(b[0]), "r"(b[1]));
}

__global__ void __launch_bounds__(256) gemm_fused(GemmParamsF p) {
    extern __shared__ __half sm[];
    const int K = p.K;
    const int stride = K + 8;            // 136 for K=128, 72 for K=64 (conflict-free)
    __half* As = sm;                     // [128][stride]
    __half* Bs = sm + 128 * stride;      // [64][stride]
    const void* A = blockIdx.y ? p.A1 : p.A0;
    const GemmJob* jobs = p.j[blockIdx.y];
    int row0 = blockIdx.x * 128;
    int t = threadIdx.x;
    int lane = t & 31;
    int warp = t >> 5;
    int g = lane >> 2;
    int tg = lane & 3;
    int wr = warp >> 1;
    int wc = warp & 1;

    // stage A once: 128 rows x K halfs
    int kq = K >> 2;               // 4-element groups per row
    int tot = 128 * kq;
    if (p.a_half) {
        const __half* Ah = (const __half*)A;
        for (int idx = t; idx < tot; idx += 256) {
            int r = idx / kq;
            int cg = (idx - r * kq) * 4;
            uint2 v = make_uint2(0u, 0u);
            if (row0 + r < p.nrows)
                v = *(const uint2*)(Ah + (size_t)(row0 + r) * CH + cg);
            *(uint2*)&As[r * stride + cg] = v;
        }
    } else {
        const float* Af = (const float*)A;
        for (int idx = t; idx < tot; idx += 256) {
            int r = idx / kq;
            int cg = (idx - r * kq) * 4;
            float4 v = make_float4(0.f, 0.f, 0.f, 0.f);
            if (row0 + r < p.nrows)
                v = *(const float4*)(Af + (size_t)(row0 + r) * CH + cg);
            __half2 h0 = __floats2half2_rn(v.x, v.y);
            __half2 h1 = __floats2half2_rn(v.z, v.w);
            uint2 pk; pk.x = *(unsigned*)&h0; pk.y = *(unsigned*)&h1;
            *(uint2*)&As[r * stride + cg] = pk;
        }
    }
    __syncthreads();

    for (int w = 0; w < p.njobs; w++) {
        GemmJob jb = jobs[w];
        // stage B transposed: W [K][64] -> Bs[n][k]
        int btot = K * 16;
        for (int idx = t; idx < btot; idx += 256) {
            int k = idx >> 4;
            int ng = (idx & 15) * 4;
            float4 v = *(const float4*)(jb.W + (size_t)k * 64 + ng);
            Bs[(ng + 0) * stride + k] = __float2half_rn(v.x);
            Bs[(ng + 1) * stride + k] = __float2half_rn(v.y);
            Bs[(ng + 2) * stride + k] = __float2half_rn(v.z);
            Bs[(ng + 3) * stride + k] = __float2half_rn(v.w);
        }
        __syncthreads();

        float acc[2][4][4];
        #pragma unroll
        for (int m = 0; m < 2; m++)
            #pragma unroll
            for (int nt = 0; nt < 4; nt++)
                #pragma unroll
                for (int i = 0; i < 4; i++) acc[m][nt][i] = 0.f;

        for (int kk = 0; kk < K; kk += 16) {
            unsigned a[2][4];
            #pragma unroll
            for (int m = 0; m < 2; m++) {
                int ar = wr * 32 + m * 16;
                a[m][0] = *(const unsigned*)&As[(ar + g) * stride + kk + tg * 2];
                a[m][1] = *(const unsigned*)&As[(ar + g + 8) * stride + kk + tg * 2];
                a[m][2] = *(const unsigned*)&As[(ar + g) * stride + kk + tg * 2 + 8];
                a[m][3] = *(const unsigned*)&As[(ar + g + 8) * stride + kk + tg * 2 + 8];
            }
            unsigned b[4][2];
            #pragma unroll
            for (int nt = 0; nt < 4; nt++) {
                int br = wc * 32 + nt * 8 + g;
                b[nt][0] = *(const unsigned*)&Bs[br * stride + kk + tg * 2];
                b[nt][1] = *(const unsigned*)&Bs[br * stride + kk + tg * 2 + 8];
            }
            #pragma unroll
            for (int m = 0; m < 2; m++)
                #pragma unroll
                for (int nt = 0; nt < 4; nt++)
                    mma16816(acc[m][nt], a[m], b[nt]);
        }

        // epilogue (always fp16 output)
        float bb0[4], bb1[4];
        #pragma unroll
        for (int nt = 0; nt < 4; nt++) {
            int col = wc * 32 + nt * 8 + tg * 2;
            bb0[nt] = jb.bias ? jb.bias[col] : 0.f;
            bb1[nt] = jb.bias ? jb.bias[col + 1] : 0.f;
        }
        #pragma unroll
        for (int m = 0; m < 2; m++) {
            int r1 = row0 + wr * 32 + m * 16 + g;
            int r2 = r1 + 8;
            #pragma unroll
            for (int nt = 0; nt < 4; nt++) {
                int col = wc * 32 + nt * 8 + tg * 2;
                if (r1 < p.nrows) {
                    __half2 h = __floats2half2_rn(acc[m][nt][0] + bb0[nt], acc[m][nt][1] + bb1[nt]);
                    *(__half2*)(jb.O + (size_t)r1 * CH + col) = h;
                }
                if (r2 < p.nrows) {
                    __half2 h = __floats2half2_rn(acc[m][nt][2] + bb0[nt], acc[m][nt][3] + bb1[nt]);
                    *(__half2*)(jb.O + (size_t)r2 * CH + col) = h;
                }
            }
        }
        __syncthreads();   // before restaging Bs
    }
}

// ---------------- layer-0 aggregation: 1 warp per node --------------------
// R fp16, Z written fp16.
__global__ void agg0_kernel(int n) {
    int w = (blockIdx.x * blockDim.x + threadIdx.x) >> 5;
    if (w >= n) return;
    int lane = threadIdx.x & 31;
    int c = lane * 2;

    float sx0 = 0.f, sy0 = 0.f, sx1 = 0.f, sy1 = 0.f;
    int b = g_rpP[w], e = g_rpP[w + 1];
    float invp = 1.0f / (float)((e - b) > 0 ? (e - b) : 1);
    int i = b;
    for (; i + 2 <= e; i += 2) {
        int ia = g_colP[i], ib = g_colP[i + 1];
        float2 ga = __half22float2(*(const __half2*)(g_U + (size_t)ia * CH + c));
        float2 gb = __half22float2(*(const __half2*)(g_U + (size_t)ib * CH + c));
        sx0 += ga.x; sy0 += ga.y; sx1 += gb.x; sy1 += gb.y;
    }
    if (i < e) {
        float2 ga = __half22float2(*(const __half2*)(g_U + (size_t)g_colP[i] * CH + c));
        sx0 += ga.x; sy0 += ga.y;
    }
    float sumpx = sx0 + sx1, sumpy = sy0 + sy1;

    float tx0 = 0.f, ty0 = 0.f, tx1 = 0.f, ty1 = 0.f;
    b = g_rpN[w]; e = g_rpN[w + 1];
    float invn = 1.0f / (float)((e - b) > 0 ? (e - b) : 1);
    i = b;
    for (; i + 2 <= e; i += 2) {
        int ia = g_colN[i], ib = g_colN[i + 1];
        float2 ga = __half22float2(*(const __half2*)(g_U + (size_t)ia * CH + 64 + c));
        float2 gb = __half22float2(*(const __half2*)(g_U + (size_t)ib * CH + 64 + c));
        tx0 += ga.x; ty0 += ga.y; tx1 += gb.x; ty1 += gb.y;
    }
    if (i < e) {
        float2 ga = __half22float2(*(const __half2*)(g_U + (size_t)g_colN[i] * CH + 64 + c));
        tx0 += ga.x; ty0 += ga.y;
    }
    float sumnx = tx0 + tx1, sumny = ty0 + ty1;

    float2 r0 = __half22float2(*(const __half2*)(g_R + (size_t)w * CH + c));
    float2 r1 = __half22float2(*(const __half2*)(g_R + (size_t)w * CH + 64 + c));
    __half2 zp = __floats2half2_rn(tanhf(r0.x + invp * sumpx), tanhf(r0.y + invp * sumpy));
    __half2 zn = __floats2half2_rn(tanhf(r1.x + invn * sumnx), tanhf(r1.y + invn * sumny));
    *(__half2*)(g_Z + (size_t)w * CH + c) = zp;
    *(__half2*)(g_Z + (size_t)w * CH + 64 + c) = zn;
}

// ---------------- loop-layer aggregation: 1 warp per node -----------------
// R fp16. Non-final: writes Z fp16. Final: writes d_out fp32.
__global__ void aggl_kernel(int n, float* __restrict__ fout, int is_final) {
    int w = (blockIdx.x * blockDim.x + threadIdx.x) >> 5;
    if (w >= n) return;
    int lane = threadIdx.x & 31;
    int c = lane * 4;

    float4 s0 = make_float4(0.f, 0.f, 0.f, 0.f);
    float4 s1 = make_float4(0.f, 0.f, 0.f, 0.f);
    int b = g_rpP[w], e = g_rpP[w + 1];
    float invp = 1.0f / (float)((e - b) > 0 ? (e - b) : 1);
    int i = b;
    for (; i + 2 <= e; i += 2) {
        int ia = g_colP[i], ib = g_colP[i + 1];
        uint2 pa = *(const uint2*)(g_U + (size_t)ia * CH + c);
        uint2 pb = *(const uint2*)(g_U + (size_t)ib * CH + c);
        float2 a0 = __half22float2(*(__half2*)&pa.x);
        float2 a1 = __half22float2(*(__half2*)&pa.y);
        float2 b0 = __half22float2(*(__half2*)&pb.x);
        float2 b1 = __half22float2(*(__half2*)&pb.y);
        s0.x += a0.x; s0.y += a0.y; s0.z += a1.x; s0.w += a1.y;
        s1.x += b0.x; s1.y += b0.y; s1.z += b1.x; s1.w += b1.y;
    }
    if (i < e) {
        uint2 pa = *(const uint2*)(g_U + (size_t)g_colP[i] * CH + c);
        float2 a0 = __half22float2(*(__half2*)&pa.x);
        float2 a1 = __half22float2(*(__half2*)&pa.y);
        s0.x += a0.x; s0.y += a0.y; s0.z += a1.x; s0.w += a1.y;
    }

    float4 t0 = make_float4(0.f, 0.f, 0.f, 0.f);
    float4 t1 = make_float4(0.f, 0.f, 0.f, 0.f);
    b = g_rpN[w]; e = g_rpN[w + 1];
    float invn = 1.0f / (float)((e - b) > 0 ? (e - b) : 1);
    i = b;
    for (; i + 2 <= e; i += 2) {
        int ia = g_colN[i], ib = g_colN[i + 1];
        uint2 pa = *(const uint2*)(g_V + (size_t)ia * CH + c);
        uint2 pb = *(const uint2*)(g_V + (size_t)ib * CH + c);
        float2 a0 = __half22float2(*(__half2*)&pa.x);
        float2 a1 = __half22float2(*(__half2*)&pa.y);
        float2 b0 = __half22float2(*(__half2*)&pb.x);
        float2 b1 = __half22float2(*(__half2*)&pb.y);
        t0.x += a0.x; t0.y += a0.y; t0.z += a1.x; t0.w += a1.y;
        t1.x += b0.x; t1.y += b0.y; t1.z += b1.x; t1.w += b1.y;
    }
    if (i < e) {
        uint2 pa = *(const uint2*)(g_V + (size_t)g_colN[i] * CH + c);
        float2 a0 = __half22float2(*(__half2*)&pa.x);
        float2 a1 = __half22float2(*(__half2*)&pa.y);
        t0.x += a0.x; t0.y += a0.y; t0.z += a1.x; t0.w += a1.y;
    }

    uint2 pr = *(const uint2*)(g_R + (size_t)w * CH + c);
    float2 r0 = __half22float2(*(__half2*)&pr.x);
    float2 r1 = __half22float2(*(__half2*)&pr.y);
    float4 o;
    o.x = tanhf(r0.x + invp * (s0.x + s1.x) + invn * (t0.x + t1.x));
    o.y = tanhf(r0.y + invp * (s0.y + s1.y) + invn * (t0.y + t1.y));
    o.z = tanhf(r1.x + invp * (s0.z + s1.z) + invn * (t0.z + t1.z));
    o.w = tanhf(r1.y + invp * (s0.w + s1.w) + invn * (t0.w + t1.w));
    if (is_final) {
        *(float4*)(fout + (size_t)w * CH + c) = o;
    } else {
        __half2 h0 = __floats2half2_rn(o.x, o.y);
        __half2 h1 = __floats2half2_rn(o.z, o.w);
        uint2 pk; pk.x = *(unsigned*)&h0; pk.y = *(unsigned*)&h1;
        *(uint2*)(g_Z + (size_t)w * CH + c) = pk;
    }
}

// ---------------- host driver --------------------------------------------
extern "C" void kernel_launch(void* const* d_in, const int* in_sizes, int n_in,
                              void* d_out, int out_size) {
    const float* x      = (const float*)d_in[0];
    const void*  pe     = d_in[1];
    const void*  nedge  = d_in[2];
    const float* Wp_l   = (const float*)d_in[3];
    const float* Wp_r   = (const float*)d_in[4];
    const float* bp     = (const float*)d_in[5];
    const float* Wn_l   = (const float*)d_in[6];
    const float* Wn_r   = (const float*)d_in[7];
    const float* bn     = (const float*)d_in[8];
    const float* Wl_pos = (const float*)d_in[9];
    const float* Wr_pos = (const float*)d_in[10];
    const float* b_pos  = (const float*)d_in[11];
    const float* Wl_neg = (const float*)d_in[12];
    const float* Wr_neg = (const float*)d_in[13];
    const float* b_neg  = (const float*)d_in[14];

    int n = in_sizes[0] / CH;
    int E = in_sizes[1] / 2;
    if (n > NN) n = NN;
    if (E > EE) E = EE;

    void *pU, *pV, *pR, *pZ, *pDegP, *pDegN;
    cudaGetSymbolAddress(&pU, g_U);
    cudaGetSymbolAddress(&pV, g_V);
    cudaGetSymbolAddress(&pR, g_R);
    cudaGetSymbolAddress(&pZ, g_Z);
    cudaGetSymbolAddress(&pDegP, g_degP);
    cudaGetSymbolAddress(&pDegN, g_degN);

    const int smem0 = (128 + 64) * (CH + 8) * 2;   // K=128 -> 52224 B
    const int smemL = (128 + 64) * (64 + 8) * 2;   // K=64  -> 27648 B
    cudaFuncSetAttribute(gemm_fused, cudaFuncAttributeMaxDynamicSharedMemorySize, smem0);

    cudaMemsetAsync(pDegP, 0, n * sizeof(int));
    cudaMemsetAsync(pDegN, 0, n * sizeof(int));

    detect_kernel<<<1, 1024>>>((const unsigned int*)pe);

    int eg = (E + 255) / 256;
    int nchunk = (n + SCHUNK - 1) / SCHUNK;
    hist2_kernel<<<dim3(eg, 2), 256>>>(pe, nedge, E);
    scan_part_kernel<<<dim3(nchunk, 2), SCHUNK>>>(n);
    scan_mid_kernel<<<1, 256>>>(nchunk);
    scan_final_kernel<<<dim3(nchunk, 2), SCHUNK>>>(n, E);
    fill2_kernel<<<dim3(eg, 2), 256>>>(pe, nedge, E);

    int mg = (n + 127) / 128;
    int wg = (n * 32 + 255) / 256;

    __half* hU = (__half*)pU;
    __half* hV = (__half*)pV;
    __half* hR = (__half*)pR;
    __half* hZ = (__half*)pZ;

    // layer 0: single fused launch, A = x (fp32) shared by 4 weights
    GemmParamsF p0;
    p0.A0 = x; p0.A1 = x; p0.a_half = 0;
    p0.njobs = 4; p0.K = CH; p0.nrows = n;
    p0.j[0][0] = GemmJob{ Wp_l, nullptr, hU };
    p0.j[0][1] = GemmJob{ Wn_l, nullptr, hU + 64 };
    p0.j[0][2] = GemmJob{ Wp_r, bp,      hR };
    p0.j[0][3] = GemmJob{ Wn_r, bn,      hR + 64 };
    p0.j[1][0] = p0.j[0][0]; p0.j[1][1] = p0.j[0][1];
    p0.j[1][2] = p0.j[0][2]; p0.j[1][3] = p0.j[0][3];
    gemm_fused<<<dim3(mg, 1), 256, smem0>>>(p0);
    agg0_kernel<<<wg, 256>>>(n);

    // loop layers: one fused launch per layer; grid.y selects zp/zn (fp16 Z)
    for (int l = 0; l < 2; l++) {
        GemmParamsF pl;
        pl.A0 = hZ; pl.A1 = hZ + 64; pl.a_half = 1;
        pl.njobs = 3; pl.K = 64; pl.nrows = n;
        // A = zp jobs
        pl.j[0][0] = GemmJob{ Wl_pos + l * 8192,        nullptr,        hU };
        pl.j[0][1] = GemmJob{ Wl_neg + l * 8192 + 4096, nullptr,        hV + 64 };
        pl.j[0][2] = GemmJob{ Wr_pos + l * 4096,        b_pos + l * 64, hR };
        pl.j[0][3] = pl.j[0][0];
        // A = zn jobs
        pl.j[1][0] = GemmJob{ Wl_neg + l * 8192,        nullptr,        hU + 64 };
        pl.j[1][1] = GemmJob{ Wl_pos + l * 8192 + 4096, nullptr,        hV };
        pl.j[1][2] = GemmJob{ Wr_neg + l * 4096,        b_neg + l * 64, hR + 64 };
        pl.j[1][3] = pl.j[1][0];
        gemm_fused<<<dim3(mg, 2), 256, smemL>>>(pl);

        aggl_kernel<<<wg, 256>>>(n, (float*)d_out, (l == 1) ? 1 : 0);
    }
}